// round 9
// baseline (speedup 1.0000x reference)
#include <cuda_runtime.h>
#include <cuda_fp16.h>
#include <cuda_fp8.h>
#include <math.h>
#include <stdint.h>

#define NS 305
#define SP 320
#define SPSP (SP * SP)
#define NB 64
#define NT 4096
#define NTAU 1023            // 4-gram steps (t=1..4092)
#define NSTEP (NTAU + 2)     // + Q-step + A-step
#define LOG_SCALE_D 8.317766166719343   // log(4096)
#define DITH1 1.0471f        // dither factor for copy 1 (compensated exactly via g_rs)

// ---------------- device globals (zero-initialized) ----------------
__device__ float g_I[SP];
__device__ __align__(16) float g_BmT[4][SP];              // BmT[a][s] = Bm[s][a]
__device__ __align__(16) float g_A32[SPSP];
__device__ __align__(16) float g_Q32[4][SPSP];
__device__ __align__(16) float g_R32[64 * SPSP];          // fp32 R_{abc}
// e5m2, 2 dither copies. Layout within one matrix (per (copy,z) slab of SPSP bytes):
// byte (row r, col c) at (( (c>>3)*5 + (r>>6) )*512 + (r&31)*16 + ((r>>5)&1)*8 + (c&7))
// => thread (col-block cb=c>>3, lane=r&31) loads uint4 covering k=2kp,2kp+1 x 8 cols,
//    warp footprint per LDG.128 = 512B contiguous (4 lines).
__device__ __align__(16) unsigned char g_S[2 * 69 * SPSP];
__device__ __align__(16) float g_rs[2 * 69 * SP];         // alpha row multiplier 4096/q per copy
__device__ unsigned char g_gram[NB * NTAU];
__device__ unsigned char g_o0[NB];
__device__ unsigned char g_tail[NB];

__device__ __forceinline__ float warpSum(float x) {
    #pragma unroll
    for (int o = 16; o; o >>= 1) x += __shfl_down_sync(0xffffffffu, x, o);
    return x;
}
__device__ __forceinline__ float warpMax(float x) {
    #pragma unroll
    for (int o = 16; o; o >>= 1) x = fmaxf(x, __shfl_down_sync(0xffffffffu, x, o));
    return x;
}
__device__ __forceinline__ float warpMaxAll(float x) {
    #pragma unroll
    for (int o = 16; o; o >>= 1) x = fmaxf(x, __shfl_xor_sync(0xffffffffu, x, o));
    return x;
}

__device__ __forceinline__ __half2 u2h(uint32_t u) { return *reinterpret_cast<__half2*>(&u); }
__device__ __forceinline__ uint32_t h2u(__half2 h) { return *reinterpret_cast<uint32_t*>(&h); }
__device__ __forceinline__ uint32_t hadd2u(uint32_t a, uint32_t b) {
    return h2u(__hadd2(u2h(a), u2h(b)));
}
__device__ __forceinline__ uint32_t s2u(const void* p) {
    uint32_t a;
    asm("{ .reg .u64 t; cvta.to.shared.u64 t, %1; cvt.u32.u64 %0, t; }" : "=r"(a) : "l"(p));
    return a;
}

// ---------------- setup: I softmax + emission softmax ----------------
__global__ void k_setup(const float* __restrict__ initk, const float* __restrict__ emisk) {
    __shared__ float red[16];
    __shared__ float bval;
    int tid = threadIdx.x, wid = tid >> 5, lane = tid & 31;
    const int nw = 16;
    float v = (tid < NS) ? initk[tid] : -1e30f;
    float m = warpMax(v);
    if (lane == 0) red[wid] = m;
    __syncthreads();
    if (tid == 0) { float mm = -1e30f; for (int w = 0; w < nw; w++) mm = fmaxf(mm, red[w]); bval = mm; }
    __syncthreads();
    m = bval;
    float e = (tid < NS) ? expf(v - m) : 0.f;
    float s = warpSum(e);
    __syncthreads();
    if (lane == 0) red[wid] = s;
    __syncthreads();
    if (tid == 0) { float ss = 0.f; for (int w = 0; w < nw; w++) ss += red[w]; bval = ss; }
    __syncthreads();
    if (tid < NS) g_I[tid] = e / bval;

    if (tid < NS) {
        float x0 = emisk[tid * 4 + 0], x1 = emisk[tid * 4 + 1];
        float x2 = emisk[tid * 4 + 2], x3 = emisk[tid * 4 + 3];
        float mm = fmaxf(fmaxf(x0, x1), fmaxf(x2, x3));
        float e0 = expf(x0 - mm), e1 = expf(x1 - mm), e2 = expf(x2 - mm), e3 = expf(x3 - mm);
        float inv = 1.f / (e0 + e1 + e2 + e3);
        g_BmT[0][tid] = e0 * inv; g_BmT[1][tid] = e1 * inv;
        g_BmT[2][tid] = e2 * inv; g_BmT[3][tid] = e3 * inv;
    }
}

// ---------------- softmax rows of transition -> A32 ----------------
__global__ void k_softA(const float* __restrict__ trans) {
    __shared__ float red[10];
    __shared__ float bval;
    int r = blockIdx.x, tid = threadIdx.x;
    int wid = tid >> 5, lane = tid & 31;
    float v = (tid < NS) ? trans[r * NS + tid] : -1e30f;
    float m = warpMax(v);
    if (lane == 0) red[wid] = m;
    __syncthreads();
    if (tid == 0) { float mm = -1e30f; for (int w = 0; w < 10; w++) mm = fmaxf(mm, red[w]); bval = mm; }
    __syncthreads();
    m = bval;
    float e = (tid < NS) ? expf(v - m) : 0.f;
    float s = warpSum(e);
    __syncthreads();
    if (lane == 0) red[wid] = s;
    __syncthreads();
    if (tid == 0) { float ss = 0.f; for (int w = 0; w < 10; w++) ss += red[w]; bval = ss; }
    __syncthreads();
    if (tid < NS) g_A32[r * SP + tid] = e / bval;
}

// ---------------- observation -> gram indices ----------------
__global__ void k_gram(const float* __restrict__ inputs) {
    int b = blockIdx.x;
    const float* inb = inputs + (size_t)b * NT * 4;
    for (int tau = threadIdx.x; tau < NTAU; tau += blockDim.x) {
        int t0 = 1 + 4 * tau;
        unsigned g = 0;
        #pragma unroll
        for (int k = 0; k < 4; k++) {
            const float* p = inb + (size_t)(t0 + k) * 4;
            float fi = p[1] + 2.f * p[2] + 3.f * p[3];
            g = (g << 2) | (unsigned)(fi + 0.5f);
        }
        g_gram[b * NTAU + tau] = (unsigned char)g;
    }
    if (threadIdx.x == 0) {
        const float* p = inb;
        g_o0[b] = (unsigned char)(p[1] + 2.f * p[2] + 3.f * p[3] + 0.5f);
        unsigned tg = 0;
        #pragma unroll
        for (int k = 0; k < 3; k++) {
            const float* q = inb + (size_t)(4093 + k) * 4;
            tg = (tg << 2) | (unsigned)(q[1] + 2.f * q[2] + 3.f * q[3] + 0.5f);
        }
        g_tail[b] = (unsigned char)tg;
    }
}

// ---------------- fp32 GEMM with k-dim column scaling ----------------
__global__ void __launch_bounds__(256) k_gemm(int mode) {
    int z = blockIdx.z;
    const float *Lp, *Rp, *sc;
    float* outf;
    if (mode == 0) {
        Lp = g_A32; Rp = g_A32; sc = g_BmT[z]; outf = g_Q32[z];
    } else {
        int a = z >> 4, bb = (z >> 2) & 3, c = z & 3;
        Lp = g_Q32[a]; sc = g_BmT[bb]; Rp = g_Q32[c]; outf = g_R32 + (size_t)z * SPSP;
    }
    int m0 = blockIdx.y * 64, n0 = blockIdx.x * 64;
    __shared__ __align__(16) float Ls[16][64];
    __shared__ __align__(16) float Rs[16][64];
    int tid = threadIdx.x;
    int tx = tid & 15, ty = tid >> 4;
    int lrow = tid >> 2, lk = (tid & 3) * 4;
    int rk = tid >> 4, rn = (tid & 15) * 4;

    float acc[4][4] = {};
    for (int k0 = 0; k0 < SP; k0 += 16) {
        float4 lv = *(const float4*)&Lp[(size_t)(m0 + lrow) * SP + k0 + lk];
        Ls[lk + 0][lrow] = lv.x * sc[k0 + lk + 0];
        Ls[lk + 1][lrow] = lv.y * sc[k0 + lk + 1];
        Ls[lk + 2][lrow] = lv.z * sc[k0 + lk + 2];
        Ls[lk + 3][lrow] = lv.w * sc[k0 + lk + 3];
        *(float4*)&Rs[rk][rn] = *(const float4*)&Rp[(size_t)(k0 + rk) * SP + n0 + rn];
        __syncthreads();
        #pragma unroll
        for (int kk = 0; kk < 16; kk++) {
            float4 av = *(const float4*)&Ls[kk][ty * 4];
            float4 bv = *(const float4*)&Rs[kk][tx * 4];
            acc[0][0] = fmaf(av.x, bv.x, acc[0][0]); acc[0][1] = fmaf(av.x, bv.y, acc[0][1]);
            acc[0][2] = fmaf(av.x, bv.z, acc[0][2]); acc[0][3] = fmaf(av.x, bv.w, acc[0][3]);
            acc[1][0] = fmaf(av.y, bv.x, acc[1][0]); acc[1][1] = fmaf(av.y, bv.y, acc[1][1]);
            acc[1][2] = fmaf(av.y, bv.z, acc[1][2]); acc[1][3] = fmaf(av.y, bv.w, acc[1][3]);
            acc[2][0] = fmaf(av.z, bv.x, acc[2][0]); acc[2][1] = fmaf(av.z, bv.y, acc[2][1]);
            acc[2][2] = fmaf(av.z, bv.z, acc[2][2]); acc[2][3] = fmaf(av.z, bv.w, acc[2][3]);
            acc[3][0] = fmaf(av.w, bv.x, acc[3][0]); acc[3][1] = fmaf(av.w, bv.y, acc[3][1]);
            acc[3][2] = fmaf(av.w, bv.z, acc[3][2]); acc[3][3] = fmaf(av.w, bv.w, acc[3][3]);
        }
        __syncthreads();
    }
    #pragma unroll
    for (int i = 0; i < 4; i++)
        #pragma unroll
        for (int j = 0; j < 4; j++)
            outf[(size_t)(m0 + ty * 4 + i) * SP + (n0 + tx * 4 + j)] = acc[i][j];
}

// ---------------- quantize to e5m2, warp-per-row, k-pair/8-col blocked layout ----------------
__global__ void k_quant() {
    int z = blockIdx.y, c = blockIdx.z;
    int warp = threadIdx.x >> 5, lane = threadIdx.x & 31;
    int r = blockIdx.x * 8 + warp;
    const float* src;
    if (z < 64) src = g_R32 + (size_t)z * SPSP;
    else if (z < 68) src = g_Q32[z - 64];
    else src = g_A32;
    const float* row = src + (size_t)r * SP;

    float vv[10];
    float mx = 0.f;
    #pragma unroll
    for (int i = 0; i < 10; i++) { vv[i] = row[lane + 32 * i]; mx = fmaxf(mx, vv[i]); }
    mx = warpMaxAll(mx);
    float q = (mx > 0.f) ? 384.f / mx : 1.f;
    if (c == 1) q *= DITH1;
    unsigned char* dst = g_S + ((size_t)c * 69 + z) * SPSP;
    int kp = r >> 6, klo = (r >> 5) & 1, rL = r & 31;
    #pragma unroll
    for (int i = 0; i < 10; i++) {
        int col = lane + 32 * i;
        dst[((col >> 3) * 5 + kp) * 512 + rL * 16 + klo * 8 + (col & 7)] =
            (unsigned char)__nv_cvt_float_to_fp8(vv[i] * q, __NV_SATFINITE, __NV_E5M2);
    }
    if (lane == 0) g_rs[(c * 69 + z) * SP + r] = 4096.f / q;
}

// ---------------- chain: 4-CTA cluster per batch, 320 threads/CTA ----------------
// CTA rank owns cols [80*rank, 80*rank+80); warp w (0..9) owns 8 cols; lane = row-class
// (rows lane+32k). 2 CTAs/SM co-resident (different clusters) hide sync latency.
// One mbarrier phase/step: local arrive 320 + remote arrives 3 peers x 40 producers = 440.
// Deferred-si (R8 semantics). logf batched via ring buffer (32 steps / flush).
__global__ void __launch_bounds__(320, 2) __cluster_dims__(4, 1, 1)
k_chain(float* __restrict__ out) {
    int tid = threadIdx.x;
    int b = blockIdx.x >> 2;
    uint32_t rank;
    asm("mov.u32 %0, %%cluster_ctarank;" : "=r"(rank));

    __shared__ __half2 ah2[2][SP];
    __shared__ __align__(16) float redp[2][40];
    __shared__ unsigned char sg[NTAU + 1];
    __shared__ float ring[32];
    __shared__ __align__(8) uint64_t mbar;
    __shared__ float pr[10];
    __shared__ float psinv;
    __shared__ float af[SP];

    int lane = tid & 31, w = tid >> 5;            // w in [0,10)
    uint32_t mbarA = s2u(&mbar);

    for (int i = tid; i < NTAU; i += 320) sg[i] = g_gram[b * NTAU + i];
    unsigned tg = g_tail[b];
    int o0 = g_o0[b];
    if (tid < 40) { redp[0][tid] = 0.f; redp[1][tid] = (tid == 0) ? 1.f : 0.f; }
    if (tid == 0)
        asm volatile("mbarrier.init.shared.b64 [%0], %1;" :: "r"(mbarA), "r"(440) : "memory");
    __syncthreads();
    asm volatile("barrier.cluster.arrive.aligned;" ::: "memory");
    asm volatile("barrier.cluster.wait.aligned;" ::: "memory");

    int z0 = sg[0] >> 2;

    // ---- prologue: every CTA builds the FULL normalized alpha0 ----
    float llf = 0.f;
    {
        float v0p = g_I[tid] * g_BmT[o0][tid];     // tid covers exactly SP=320
        float wsum = warpSum(v0p);
        if (lane == 0) pr[w] = wsum;
        __syncthreads();
        if (tid == 0) {
            float x = 0.f;
            #pragma unroll
            for (int q = 0; q < 10; q++) x += pr[q];
            psinv = 1.f / x;
            pr[0] = x;
        }
        __syncthreads();
        llf = logf(pr[0]);
        af[tid] = v0p * psinv;
        __syncthreads();
        if (tid < 160) {
            float2 rsv = *(const float2*)&g_rs[z0 * SP + 2 * tid];   // step 0 = copy 0
            float a0 = af[2 * tid] * rsv.x, a1 = af[2 * tid + 1] * rsv.y;
            ah2[0][2 * tid]     = __floats2half2_rn(a0, a0);
            ah2[0][2 * tid + 1] = __floats2half2_rn(a1, a1);
        }
        __syncthreads();
    }

    int cb = (int)rank * 10 + w;                   // 8-col block index (c>>3)
    int gcol = (int)rank * 80 + 8 * w + 2 * (lane & 3);
    int slot = (int)rank * 10 + w;
    int bit0 = lane & 1, bit1 = (lane >> 1) & 1;

    // ---- preload mr for step 0 (copy 0): uint4 covers k=2kp,2kp+1 x 8 cols ----
    uint4 mr[5];
    {
        const uint4* base = (const uint4*)(g_S + (size_t)z0 * SPSP);
        #pragma unroll
        for (int kp = 0; kp < 5; kp++) mr[kp] = __ldcg(base + (cb * 5 + kp) * 32 + lane);
    }

    for (int step = 0; step < NSTEP; ++step) {
        int pb = step & 1, nb = 1 - pb;
        int d, zn;
        if (step < NTAU) d = sg[step] & 3;
        else if (step == NTAU) d = (tg >> 2) & 3;
        else d = tg & 3;
        if (step + 1 < NTAU) zn = sg[step + 1] >> 2;
        else if (step + 1 == NTAU) zn = 64 + ((tg >> 4) & 3);
        else zn = 68;
        int zoff = nb * 69 + zn;

        // si_prev from last step's 40 partials
        float tot = 0.f;
        #pragma unroll
        for (int q = 0; q < 10; q++) {
            float4 t = *(const float4*)&redp[nb][4 * q];
            tot += (t.x + t.y) + (t.z + t.w);
        }
        float si = __frcp_rn(tot);
        if (rank == 0) {
            if (tid == 0) ring[step & 31] = tot;   // stash; logs batched below
            if (w == 0 && (step & 31) == 31) {
                __syncwarp();
                float x = logf(ring[lane]);
                x = warpSum(x);
                if (lane == 0) llf += x;
            }
        }

        float2 fo  = *(const float2*)&g_BmT[d][gcol];
        float2 rsv = *(const float2*)&g_rs[(size_t)zoff * SP + gcol];

        // ---- FMA phase: 8 cols, rows lane+32k; mr[kp] = {k even cols0-3, cols4-7, k odd ...} ----
        __half2 a0 = __floats2half2_rn(0.f, 0.f);
        __half2 a1 = a0, a2 = a0, a3 = a0;
        #pragma unroll
        for (int kp = 0; kp < 5; kp++) {
            __half2 av0 = ah2[pb][lane + 64 * kp];
            __half2 av1 = ah2[pb][lane + 64 * kp + 32];
            a0 = __hfma2(av0, u2h(__byte_perm(mr[kp].x, 0, 0x1404)), a0);
            a1 = __hfma2(av0, u2h(__byte_perm(mr[kp].x, 0, 0x3424)), a1);
            a2 = __hfma2(av0, u2h(__byte_perm(mr[kp].y, 0, 0x1404)), a2);
            a3 = __hfma2(av0, u2h(__byte_perm(mr[kp].y, 0, 0x3424)), a3);
            a0 = __hfma2(av1, u2h(__byte_perm(mr[kp].z, 0, 0x1404)), a0);
            a1 = __hfma2(av1, u2h(__byte_perm(mr[kp].z, 0, 0x3424)), a1);
            a2 = __hfma2(av1, u2h(__byte_perm(mr[kp].w, 0, 0x1404)), a2);
            a3 = __hfma2(av1, u2h(__byte_perm(mr[kp].w, 0, 0x3424)), a3);
        }

        // ---- in-warp reduce: lane ends holding col-pair (lane&3) total ----
        uint32_t h0 = h2u(a0), h1 = h2u(a1), h2v = h2u(a2), h3 = h2u(a3);
        {
            uint32_t g0 = bit0 ? h0 : h1, g1 = bit0 ? h2v : h3;
            uint32_t r0 = __shfl_xor_sync(0xffffffffu, g0, 1);
            uint32_t r1 = __shfl_xor_sync(0xffffffffu, g1, 1);
            h0 = hadd2u(bit0 ? h1 : h0, r0);
            h1 = hadd2u(bit0 ? h3 : h2v, r1);
        }
        {
            uint32_t g0 = bit1 ? h0 : h1;
            uint32_t r0 = __shfl_xor_sync(0xffffffffu, g0, 2);
            h0 = hadd2u(bit1 ? h1 : h0, r0);
        }
        h0 = hadd2u(h0, __shfl_xor_sync(0xffffffffu, h0, 4));
        h0 = hadd2u(h0, __shfl_xor_sync(0xffffffffu, h0, 8));
        h0 = hadd2u(h0, __shfl_xor_sync(0xffffffffu, h0, 16));

        // ---- producers (lanes 0-3): finish own 2 cols, write local + 3 peers ----
        float p = 0.f;
        if (lane < 4) {
            float2 f2 = __half22float2(u2h(h0));
            float v0 = f2.x * fo.x * si, v1 = f2.y * fo.y * si;
            float b0 = v0 * rsv.x, b1 = v1 * rsv.y;   // next alpha, un-si'd (deferred)
            uint32_t pkx = h2u(__floats2half2_rn(b0, b0));
            uint32_t pky = h2u(__floats2half2_rn(b1, b1));
            *(uint2*)&ah2[nb][gcol] = make_uint2(pkx, pky);
            uint64_t vv = ((uint64_t)pky << 32) | pkx;
            uint32_t la = s2u(&ah2[nb][gcol]);
            #pragma unroll
            for (int pi = 1; pi < 4; pi++) {
                uint32_t peer = (rank + pi) & 3;
                asm volatile(
                    "{ .reg .b32 ra; mapa.shared::cluster.u32 ra, %0, %1;"
                    "  st.shared::cluster.b64 [ra], %2; }"
                    :: "r"(la), "r"(peer), "l"(vv) : "memory");
            }
            p = v0 + v1;
        }
        p += __shfl_xor_sync(0xffffffffu, p, 1);
        p += __shfl_xor_sync(0xffffffffu, p, 2);
        if (lane == 0) {
            redp[pb][slot] = p;
            uint32_t la = s2u(&redp[pb][slot]);
            #pragma unroll
            for (int pi = 1; pi < 4; pi++) {
                uint32_t peer = (rank + pi) & 3;
                asm volatile(
                    "{ .reg .b32 ra; mapa.shared::cluster.u32 ra, %0, %1;"
                    "  st.shared::cluster.b32 [ra], %2; }"
                    :: "r"(la), "r"(peer), "f"(p) : "memory");
            }
        }
        // remote arrives (after this thread's remote stores), then local arrive
        if (lane < 4) {
            #pragma unroll
            for (int pi = 1; pi < 4; pi++) {
                uint32_t peer = (rank + pi) & 3;
                asm volatile(
                    "{ .reg .b32 ra; mapa.shared::cluster.u32 ra, %0, %1;"
                    "  mbarrier.arrive.shared::cluster.b64 _, [ra]; }"
                    :: "r"(mbarA), "r"(peer) : "memory");
            }
        }
        asm volatile("mbarrier.arrive.shared.b64 _, [%0];" :: "r"(mbarA) : "memory");

        // ---- issue next step's mr loads while the barrier settles ----
        {
            const uint4* base = (const uint4*)(g_S + (size_t)zoff * SPSP);
            #pragma unroll
            for (int kp = 0; kp < 5; kp++) mr[kp] = __ldcg(base + (cb * 5 + kp) * 32 + lane);
        }

        // ---- wait for phase completion (440 arrives), cluster-acquire ----
        {
            uint32_t parity = (uint32_t)(step & 1);
            uint32_t done;
            asm volatile(
                "{ .reg .pred P;"
                "  mbarrier.try_wait.parity.acquire.cluster.shared::cta.b64 P, [%1], %2;"
                "  selp.b32 %0, 1, 0, P; }"
                : "=r"(done) : "r"(mbarA), "r"(parity) : "memory");
            if (!done) {
                asm volatile(
                    "{ .reg .pred P;"
                    "WL_%=:"
                    "  mbarrier.try_wait.parity.acquire.cluster.shared::cta.b64 P, [%0], %1, 0x989680;"
                    "  @P bra WD_%=;"
                    "  bra WL_%=;"
                    "WD_%=: }"
                    :: "r"(mbarA), "r"(parity) : "memory");
            }
        }
    }

    if (rank == 0 && tid == 0) {
        int fb = (NSTEP - 1) & 1;                    // buffer holding s_{NSTEP-1}
        float tot = 0.f;
        #pragma unroll
        for (int q = 0; q < 40; q++) tot += redp[fb][q];
        llf += logf(ring[(NSTEP - 1) & 31]);         // iteration 1024's stash (s_1023)
        llf += logf(tot);                            // s_1024
        out[b] = (float)((double)llf - (double)NSTEP * LOG_SCALE_D);
    }
}

// ---------------- launch ----------------
extern "C" void kernel_launch(void* const* d_in, const int* in_sizes, int n_in,
                              void* d_out, int out_size) {
    const float* inputs = (const float*)d_in[0];
    const float* initk  = (const float*)d_in[1];
    const float* transk = (const float*)d_in[2];
    const float* emisk  = (const float*)d_in[3];
    float* out = (float*)d_out;

    k_setup<<<1, 512>>>(initk, emisk);
    k_softA<<<NS, 320>>>(transk);
    k_gram<<<NB, 256>>>(inputs);
    k_gemm<<<dim3(5, 5, 4), 256>>>(0);
    k_gemm<<<dim3(5, 5, 64), 256>>>(1);
    k_quant<<<dim3(40, 69, 2), 256>>>();
    k_chain<<<NB * 4, 320>>>(out);
}

// round 10
// speedup vs baseline: 1.0296x; 1.0296x over previous
#include <cuda_runtime.h>
#include <cuda_fp16.h>
#include <cuda_fp8.h>
#include <mma.h>
#include <math.h>
#include <stdint.h>

using namespace nvcuda;

#define NS 305
#define SP 320
#define SPSP (SP * SP)
#define NB 64
#define NT 4096
#define NSTEP 819            // 5-gram supersteps: 1 + 5*819 = 4096 exactly
#define NMAT 256             // 4^4 composite matrices
#define LOG_SCALE_D 8.317766166719343   // log(4096)
#define DITH1 1.0471f        // dither factor for copy 1 (compensated exactly via g_rs)

// ---------------- device globals (zero-initialized) ----------------
__device__ float g_I[SP];
__device__ __align__(16) float g_BmT[4][SP];              // BmT[a][s] = Bm[s][a]
__device__ __align__(16) __half g_A16[SPSP];              // softmax(A), fp16
__device__ __align__(16) __half g_Q16[4][SPSP];           // Q_a = (A Da) A
__device__ __align__(16) __half g_U16[16][SPSP];          // U_cd = (Q_c Dd) A
__device__ __align__(16) __half g_M16[(size_t)NMAT * SPSP];  // M_abcd = (Q_a Db) U_cd
// e5m2, 2 dither copies, 8-col blocked: byte (r,c) at ((r>>5)*40 + (c>>3))*256 + (r&31)*8 + (c&7)
__device__ __align__(16) unsigned char g_S[2ull * NMAT * SPSP];
__device__ __align__(16) float g_rs[2 * NMAT * SP];       // alpha row multiplier 4096/q per copy
__device__ unsigned short g_gram[NB * NSTEP];             // (z<<2)|fold, z in 0..255
__device__ unsigned char g_o0[NB];

__device__ __forceinline__ float warpSum(float x) {
    #pragma unroll
    for (int o = 16; o; o >>= 1) x += __shfl_down_sync(0xffffffffu, x, o);
    return x;
}
__device__ __forceinline__ float warpMax(float x) {
    #pragma unroll
    for (int o = 16; o; o >>= 1) x = fmaxf(x, __shfl_down_sync(0xffffffffu, x, o));
    return x;
}
__device__ __forceinline__ float warpMaxAll(float x) {
    #pragma unroll
    for (int o = 16; o; o >>= 1) x = fmaxf(x, __shfl_xor_sync(0xffffffffu, x, o));
    return x;
}
__device__ __forceinline__ __half2 u2h(uint32_t u) { return *reinterpret_cast<__half2*>(&u); }
__device__ __forceinline__ uint32_t h2u(__half2 h) { return *reinterpret_cast<uint32_t*>(&h); }
__device__ __forceinline__ uint32_t hadd2u(uint32_t a, uint32_t b) {
    return h2u(__hadd2(u2h(a), u2h(b)));
}
__device__ __forceinline__ uint32_t s2u(const void* p) {
    uint32_t a;
    asm("{ .reg .u64 t; cvta.to.shared.u64 t, %1; cvt.u32.u64 %0, t; }" : "=r"(a) : "l"(p));
    return a;
}

// ---------------- setup: I softmax + emission softmax ----------------
__global__ void k_setup(const float* __restrict__ initk, const float* __restrict__ emisk) {
    __shared__ float red[16];
    __shared__ float bval;
    int tid = threadIdx.x, wid = tid >> 5, lane = tid & 31;
    const int nw = 16;
    float v = (tid < NS) ? initk[tid] : -1e30f;
    float m = warpMax(v);
    if (lane == 0) red[wid] = m;
    __syncthreads();
    if (tid == 0) { float mm = -1e30f; for (int w = 0; w < nw; w++) mm = fmaxf(mm, red[w]); bval = mm; }
    __syncthreads();
    m = bval;
    float e = (tid < NS) ? expf(v - m) : 0.f;
    float s = warpSum(e);
    __syncthreads();
    if (lane == 0) red[wid] = s;
    __syncthreads();
    if (tid == 0) { float ss = 0.f; for (int w = 0; w < nw; w++) ss += red[w]; bval = ss; }
    __syncthreads();
    if (tid < NS) g_I[tid] = e / bval;

    if (tid < NS) {
        float x0 = emisk[tid * 4 + 0], x1 = emisk[tid * 4 + 1];
        float x2 = emisk[tid * 4 + 2], x3 = emisk[tid * 4 + 3];
        float mm = fmaxf(fmaxf(x0, x1), fmaxf(x2, x3));
        float e0 = expf(x0 - mm), e1 = expf(x1 - mm), e2 = expf(x2 - mm), e3 = expf(x3 - mm);
        float inv = 1.f / (e0 + e1 + e2 + e3);
        g_BmT[0][tid] = e0 * inv; g_BmT[1][tid] = e1 * inv;
        g_BmT[2][tid] = e2 * inv; g_BmT[3][tid] = e3 * inv;
    }
}

// ---------------- softmax rows of transition -> A16 ----------------
__global__ void k_softA(const float* __restrict__ trans) {
    __shared__ float red[10];
    __shared__ float bval;
    int r = blockIdx.x, tid = threadIdx.x;
    int wid = tid >> 5, lane = tid & 31;
    float v = (tid < NS) ? trans[r * NS + tid] : -1e30f;
    float m = warpMax(v);
    if (lane == 0) red[wid] = m;
    __syncthreads();
    if (tid == 0) { float mm = -1e30f; for (int w = 0; w < 10; w++) mm = fmaxf(mm, red[w]); bval = mm; }
    __syncthreads();
    m = bval;
    float e = (tid < NS) ? expf(v - m) : 0.f;
    float s = warpSum(e);
    __syncthreads();
    if (lane == 0) red[wid] = s;
    __syncthreads();
    if (tid == 0) { float ss = 0.f; for (int w = 0; w < 10; w++) ss += red[w]; bval = ss; }
    __syncthreads();
    if (tid < NS) g_A16[r * SP + tid] = __float2half_rn(e / bval);
}

// ---------------- observation -> 5-gram indices ----------------
__global__ void k_gram(const float* __restrict__ inputs) {
    int b = blockIdx.x;
    const float* inb = inputs + (size_t)b * NT * 4;
    for (int tau = threadIdx.x; tau < NSTEP; tau += blockDim.x) {
        int t0 = 1 + 5 * tau;
        unsigned g = 0;
        #pragma unroll
        for (int k = 0; k < 5; k++) {
            const float* p = inb + (size_t)(t0 + k) * 4;
            float fi = p[1] + 2.f * p[2] + 3.f * p[3];   // exact argmax of one-hot
            g = (g << 2) | (unsigned)(fi + 0.5f);
        }
        g_gram[b * NSTEP + tau] = (unsigned short)g;      // z = g>>2 (8b), fold = g&3
    }
    if (threadIdx.x == 0) {
        const float* p = inb;
        g_o0[b] = (unsigned char)(p[1] + 2.f * p[2] + 3.f * p[3] + 0.5f);
    }
}

// ---------------- wmma fp16 GEMM: C = (L * diag(sc)) @ R, all [320,320] half ----------------
// mode 0: Q_z = (A*Dz)@A (z<4); mode 1: U_z = (Q_{z>>2}*D_{z&3})@A (z<16);
// mode 2: M_z = (Q_{z>>6}*D_{(z>>4)&3})@U_{z&15} (z<256)
__global__ void __launch_bounds__(256) k_gemm_h(int mode) {
    int z = blockIdx.z;
    const __half *Lp, *Rp;
    const float* sc;
    __half* outp;
    if (mode == 0)      { Lp = g_A16;        sc = g_BmT[z];           Rp = g_A16;        outp = g_Q16[z]; }
    else if (mode == 1) { Lp = g_Q16[z >> 2]; sc = g_BmT[z & 3];      Rp = g_A16;        outp = g_U16[z]; }
    else                { Lp = g_Q16[z >> 6]; sc = g_BmT[(z >> 4) & 3]; Rp = g_U16[z & 15]; outp = g_M16 + (size_t)z * SPSP; }
    int m0 = blockIdx.y * 64, n0 = blockIdx.x * 64;

    __shared__ __align__(16) __half As[64][72];
    __shared__ __align__(16) __half Bs[64][72];
    __shared__ __align__(16) float Cs[64][68];

    int tid = threadIdx.x;
    int w = tid >> 5;
    int wm = w & 3, wn = w >> 2;                 // 4 M-blocks x 2 N-blocks (16x32 per warp)
    int lr = tid >> 2, lc = (tid & 3) * 16;

    wmma::fragment<wmma::accumulator, 16, 16, 16, float> cf[2];
    wmma::fill_fragment(cf[0], 0.f);
    wmma::fill_fragment(cf[1], 0.f);

    for (int k0 = 0; k0 < SP; k0 += 64) {
        #pragma unroll
        for (int j = 0; j < 16; j += 2) {
            __half2 lv = *(const __half2*)&Lp[(size_t)(m0 + lr) * SP + k0 + lc + j];
            float2 sv = *(const float2*)&sc[k0 + lc + j];
            float2 lf = __half22float2(lv);
            *(__half2*)&As[lr][lc + j] = __floats2half2_rn(lf.x * sv.x, lf.y * sv.y);
            *(__half2*)&Bs[lr][lc + j] = *(const __half2*)&Rp[(size_t)(k0 + lr) * SP + n0 + lc + j];
        }
        __syncthreads();
        #pragma unroll
        for (int kk = 0; kk < 4; kk++) {
            wmma::fragment<wmma::matrix_a, 16, 16, 16, __half, wmma::row_major> af;
            wmma::load_matrix_sync(af, &As[wm * 16][kk * 16], 72);
            #pragma unroll
            for (int nn = 0; nn < 2; nn++) {
                wmma::fragment<wmma::matrix_b, 16, 16, 16, __half, wmma::row_major> bf;
                wmma::load_matrix_sync(bf, &Bs[kk * 16][wn * 32 + nn * 16], 72);
                wmma::mma_sync(cf[nn], af, bf, cf[nn]);
            }
        }
        __syncthreads();
    }
    wmma::store_matrix_sync(&Cs[wm * 16][wn * 32 + 0], cf[0], 68, wmma::mem_row_major);
    wmma::store_matrix_sync(&Cs[wm * 16][wn * 32 + 16], cf[1], 68, wmma::mem_row_major);
    __syncthreads();
    #pragma unroll
    for (int j = 0; j < 16; j++)
        outp[(size_t)(m0 + lr) * SP + n0 + lc + j] = __float2half_rn(Cs[lr][lc + j]);
}

// ---------------- quantize M to e5m2, warp-per-row, 8-col blocked, 2 dithered copies ----------------
// grid (40, 256, 2), block 256 (8 warps; warp handles row blockIdx.x*8+warp)
__global__ void k_quant() {
    int z = blockIdx.y, c = blockIdx.z;
    int warp = threadIdx.x >> 5, lane = threadIdx.x & 31;
    int r = blockIdx.x * 8 + warp;
    const __half* row = g_M16 + (size_t)z * SPSP + (size_t)r * SP;

    float vv[10];
    float mx = 0.f;
    #pragma unroll
    for (int i = 0; i < 10; i++) { vv[i] = __half2float(row[lane + 32 * i]); mx = fmaxf(mx, vv[i]); }
    mx = warpMaxAll(mx);
    float q = (mx > 0.f) ? 384.f / mx : 1.f;
    if (c == 1) q *= DITH1;
    unsigned char* dst = g_S + ((size_t)c * NMAT + z) * SPSP;
    int rk = r >> 5, rL = r & 31;
    #pragma unroll
    for (int i = 0; i < 10; i++) {
        int col = lane + 32 * i;
        dst[(((rk * 40 + (col >> 3)) * 32 + rL) << 3) + (col & 7)] =
            (unsigned char)__nv_cvt_float_to_fp8(vv[i] * q, __NV_SATFINITE, __NV_E5M2);
    }
    if (lane == 0) g_rs[(c * NMAT + z) * SP + r] = 4096.f / q;
}

// ---------------- chain: 2-CTA cluster per batch, 819 homogeneous supersteps ----------------
// R8 structure verbatim: CTA rank owns cols [160*rank,160*rank+160); warp w owns 8 cols;
// lane = row-class (rows lane+32k). One mbarrier phase/step (arrives 640 local + 80 remote = 720).
// Deferred-si; Kahan float log accumulation on rank0/tid0.
__global__ void __launch_bounds__(640, 1) __cluster_dims__(2, 1, 1)
k_chain(float* __restrict__ out) {
    int tid = threadIdx.x;
    int b = blockIdx.x >> 1;
    uint32_t rank;
    asm("mov.u32 %0, %%cluster_ctarank;" : "=r"(rank));
    int peer = 1 - (int)rank;

    __shared__ __half2 ah2[2][SP];
    __shared__ __align__(16) float redp[2][48];    // slots 0..39 used (rank*20 + w)
    __shared__ unsigned short sg[NSTEP + 1];
    __shared__ __align__(8) uint64_t mbar;
    __shared__ float pr[20];
    __shared__ float psinv;
    __shared__ float af[SP];

    int lane = tid & 31, w = tid >> 5;
    uint32_t mbarA = s2u(&mbar);

    for (int i = tid; i < NSTEP; i += 640) sg[i] = g_gram[b * NSTEP + i];
    int o0 = g_o0[b];
    if (tid == 0) sg[NSTEP] = 0;                   // sentinel for step+1 lookahead
    if (tid < 48) { redp[0][tid] = 0.f; redp[1][tid] = (tid == 0) ? 1.f : 0.f; }
    if (tid == 0)
        asm volatile("mbarrier.init.shared.b64 [%0], %1;" :: "r"(mbarA), "r"(720) : "memory");
    __syncthreads();
    asm volatile("barrier.cluster.arrive.aligned;" ::: "memory");
    asm volatile("barrier.cluster.wait.aligned;" ::: "memory");

    int z0 = sg[0] >> 2;

    // ---- prologue: both CTAs build the FULL normalized alpha0 ----
    float llf = 0.f, lcomp = 0.f;
    {
        float v0p = (tid < SP) ? g_I[tid] * g_BmT[o0][tid] : 0.f;
        float wsum = warpSum(v0p);
        if (lane == 0) pr[w] = wsum;
        __syncthreads();
        if (tid == 0) {
            float x = 0.f;
            #pragma unroll
            for (int q = 0; q < 20; q++) x += pr[q];
            psinv = 1.f / x;
            pr[0] = x;
        }
        __syncthreads();
        llf = logf(pr[0]);
        if (tid < SP) af[tid] = v0p * psinv;
        __syncthreads();
        if (tid < 160) {
            float2 rsv = *(const float2*)&g_rs[z0 * SP + 2 * tid];   // step 0 = copy 0
            float a0 = af[2 * tid] * rsv.x, a1 = af[2 * tid + 1] * rsv.y;
            ah2[0][2 * tid]     = __floats2half2_rn(a0, a0);
            ah2[0][2 * tid + 1] = __floats2half2_rn(a1, a1);
        }
        __syncthreads();
    }

    int cb = (int)rank * 20 + w;                   // 8-col block index owned by this warp
    int gcol = (int)rank * 160 + 8 * w + 2 * (lane & 3);
    int slot = (int)rank * 20 + w;
    int bit0 = lane & 1, bit1 = (lane >> 1) & 1;

    // ---- preload mr for step 0 (copy 0) ----
    uint2 mr[10];
    {
        const uint2* base = (const uint2*)(g_S + (size_t)z0 * SPSP);
        #pragma unroll
        for (int k = 0; k < 10; k++) mr[k] = __ldcg(base + (k * 40 + cb) * 32 + lane);
    }

    for (int step = 0; step < NSTEP; ++step) {
        int pb = step & 1, nb = 1 - pb;
        int d = sg[step] & 3;
        int zn = sg[step + 1] >> 2;                // sentinel makes last lookahead safe
        int zoff = nb * NMAT + zn;                 // dither copy alternates by step

        // si_prev from last step's 40 global partials (fills mr-load latency window)
        float tot = 0.f;
        #pragma unroll
        for (int q = 0; q < 10; q++) {
            float4 t = *(const float4*)&redp[nb][4 * q];
            tot += (t.x + t.y) + (t.z + t.w);
        }
        float si = __frcp_rn(tot);
        if (rank == 0 && tid == 0) {               // Kahan log of s_{step-1} (log(1)=0 at step 0)
            float y = logf(tot) - lcomp;
            float t2 = llf + y;
            lcomp = (t2 - llf) - y;
            llf = t2;
        }
        float2 fo  = *(const float2*)&g_BmT[d][gcol];
        float2 rsv = *(const float2*)&g_rs[(size_t)zoff * SP + gcol];

        // ---- FMA phase: 8 cols, rows lane+32k ----
        __half2 a0 = __floats2half2_rn(0.f, 0.f);
        __half2 a1 = a0, a2 = a0, a3 = a0;
        #pragma unroll
        for (int k = 0; k < 10; k++) {
            __half2 av = ah2[pb][lane + 32 * k];
            a0 = __hfma2(av, u2h(__byte_perm(mr[k].x, 0, 0x1404)), a0);
            a1 = __hfma2(av, u2h(__byte_perm(mr[k].x, 0, 0x3424)), a1);
            a2 = __hfma2(av, u2h(__byte_perm(mr[k].y, 0, 0x1404)), a2);
            a3 = __hfma2(av, u2h(__byte_perm(mr[k].y, 0, 0x3424)), a3);
        }

        // ---- in-warp reduce: lane ends holding col-pair (lane&3) total ----
        uint32_t h0 = h2u(a0), h1 = h2u(a1), h2v = h2u(a2), h3 = h2u(a3);
        {
            uint32_t g0 = bit0 ? h0 : h1, g1 = bit0 ? h2v : h3;
            uint32_t r0 = __shfl_xor_sync(0xffffffffu, g0, 1);
            uint32_t r1 = __shfl_xor_sync(0xffffffffu, g1, 1);
            h0 = hadd2u(bit0 ? h1 : h0, r0);
            h1 = hadd2u(bit0 ? h3 : h2v, r1);
        }
        {
            uint32_t g0 = bit1 ? h0 : h1;
            uint32_t r0 = __shfl_xor_sync(0xffffffffu, g0, 2);
            h0 = hadd2u(bit1 ? h1 : h0, r0);
        }
        h0 = hadd2u(h0, __shfl_xor_sync(0xffffffffu, h0, 4));
        h0 = hadd2u(h0, __shfl_xor_sync(0xffffffffu, h0, 8));
        h0 = hadd2u(h0, __shfl_xor_sync(0xffffffffu, h0, 16));

        // ---- lanes 0-3: finish own 2 cols, write local + remote alpha ----
        float p = 0.f;
        if (lane < 4) {
            float2 f2 = __half22float2(u2h(h0));
            float v0 = f2.x * fo.x * si, v1 = f2.y * fo.y * si;
            float b0 = v0 * rsv.x, b1 = v1 * rsv.y;   // next alpha, un-si'd (deferred)
            uint32_t pkx = h2u(__floats2half2_rn(b0, b0));
            uint32_t pky = h2u(__floats2half2_rn(b1, b1));
            *(uint2*)&ah2[nb][gcol] = make_uint2(pkx, pky);
            uint64_t vv = ((uint64_t)pky << 32) | pkx;
            uint32_t la = s2u(&ah2[nb][gcol]);
            asm volatile(
                "{ .reg .b32 ra; mapa.shared::cluster.u32 ra, %0, %1;"
                "  st.shared::cluster.b64 [ra], %2; }"
                :: "r"(la), "r"(peer), "l"(vv) : "memory");
            p = v0 + v1;
        }
        p += __shfl_xor_sync(0xffffffffu, p, 1);
        p += __shfl_xor_sync(0xffffffffu, p, 2);
        if (lane == 0) {
            redp[pb][slot] = p;
            uint32_t la = s2u(&redp[pb][slot]);
            asm volatile(
                "{ .reg .b32 ra; mapa.shared::cluster.u32 ra, %0, %1;"
                "  st.shared::cluster.b32 [ra], %2; }"
                :: "r"(la), "r"(peer), "f"(p) : "memory");
        }
        if (lane < 4) {
            asm volatile(
                "{ .reg .b32 ra; mapa.shared::cluster.u32 ra, %0, %1;"
                "  mbarrier.arrive.shared::cluster.b64 _, [ra]; }"
                :: "r"(mbarA), "r"(peer) : "memory");
        }
        asm volatile("mbarrier.arrive.shared.b64 _, [%0];" :: "r"(mbarA) : "memory");

        // ---- issue next step's mr loads while the barrier settles ----
        {
            const uint2* base = (const uint2*)(g_S + (size_t)zoff * SPSP);
            #pragma unroll
            for (int k = 0; k < 10; k++) mr[k] = __ldcg(base + (k * 40 + cb) * 32 + lane);
        }

        // ---- wait for phase completion (720 arrives), cluster-acquire ----
        {
            uint32_t parity = (uint32_t)(step & 1);
            uint32_t done;
            asm volatile(
                "{ .reg .pred P;"
                "  mbarrier.try_wait.parity.acquire.cluster.shared::cta.b64 P, [%1], %2;"
                "  selp.b32 %0, 1, 0, P; }"
                : "=r"(done) : "r"(mbarA), "r"(parity) : "memory");
            if (!done) {
                asm volatile(
                    "{ .reg .pred P;"
                    "WL_%=:"
                    "  mbarrier.try_wait.parity.acquire.cluster.shared::cta.b64 P, [%0], %1, 0x989680;"
                    "  @P bra WD_%=;"
                    "  bra WL_%=;"
                    "WD_%=: }"
                    :: "r"(mbarA), "r"(parity) : "memory");
            }
        }
    }

    if (rank == 0 && tid == 0) {
        int fb = (NSTEP - 1) & 1;                    // buffer holding s_{NSTEP-1}
        float tot = 0.f;
        #pragma unroll
        for (int q = 0; q < 40; q++) tot += redp[fb][q];
        llf += logf(tot);
        out[b] = (float)((double)llf - (double)NSTEP * LOG_SCALE_D);
    }
}

// ---------------- launch ----------------
extern "C" void kernel_launch(void* const* d_in, const int* in_sizes, int n_in,
                              void* d_out, int out_size) {
    const float* inputs = (const float*)d_in[0];
    const float* initk  = (const float*)d_in[1];
    const float* transk = (const float*)d_in[2];
    const float* emisk  = (const float*)d_in[3];
    float* out = (float*)d_out;

    k_setup<<<1, 512>>>(initk, emisk);
    k_softA<<<NS, 320>>>(transk);
    k_gram<<<NB, 256>>>(inputs);
    k_gemm_h<<<dim3(5, 5, 4), 256>>>(0);     // Q_a
    k_gemm_h<<<dim3(5, 5, 16), 256>>>(1);    // U_cd
    k_gemm_h<<<dim3(5, 5, 256), 256>>>(2);   // M_abcd
    k_quant<<<dim3(40, 256, 2), 256>>>();
    k_chain<<<NB * 2, 640>>>(out);
}